// round 12
// baseline (speedup 1.0000x reference)
#include <cuda_runtime.h>
#include <cstdint>

#define N_CTRL   256
#define KLEN     260     // N_CTRL + DEGREE + 1
#define OUT_X    1024
#define OUT_Y    1024
#define DEG      3
#define EPS_     1e-05

// ---------------- device scratch (no allocations allowed) ----------------
__device__ float4 g_bx[OUT_X];
__device__ float4 g_by[OUT_Y];
__device__ int4   g_ix[OUT_X];
__device__ int4   g_iy[OUT_Y];
__device__ float4 g_cp4[N_CTRL * N_CTRL];        // 1 MB packed control points
__device__ float4 g_T[N_CTRL * OUT_Y];           // 4 MB intermediate T[i][f]

__device__ __forceinline__ int imod(int a, int m) {
    int r = a % m;
    return r < 0 ? r + m : r;
}

// ---------------- kernel 1: fused prep --------------------------------
// blocks 0,1 : normalize knots (warp scan in smem) + basis + indices
// blocks 2..65 : pack control points into float4
__global__ void prep_kernel(const float* __restrict__ cp,
                            const float* __restrict__ kx_in,
                            const float* __restrict__ ky_in) {
    int b = blockIdx.x;
    if (b < 2) {
        __shared__ float kn[KLEN];
        const float* in = (b == 0) ? kx_in : ky_in;

        // ---- warp 0: inclusive scan of clamped knots into smem ----
        if (threadIdx.x < 32) {
            int lane = threadIdx.x;
            float carry = 0.f;
            for (int base = 0; base < KLEN; base += 32) {
                int idx = base + lane;
                float v = 0.f;
                if (idx < KLEN) {
                    v = in[idx];
                    if (v < 0.f) v = 1e-4f;   // jnp.where(k < 0, 0.0001, k)
                }
                #pragma unroll
                for (int off = 1; off < 32; off <<= 1) {
                    float n = __shfl_up_sync(0xffffffffu, v, off);
                    if (lane >= off) v += n;
                }
                if (idx < KLEN) kn[idx] = v + carry;
                carry += __shfl_sync(0xffffffffu, v, 31);
            }
        }
        __syncthreads();

        // ---- normalize in place ----
        float k0   = kn[0];
        float kend = kn[KLEN - 1];
        float inv  = 1.f / (kend - k0);
        __syncthreads();                 // everyone read k0/kend before writes
        for (int i = threadIdx.x; i < KLEN; i += blockDim.x)
            kn[i] = (kn[i] - k0) * inv;
        __syncthreads();

        // ---- per-sample span + Cox-de Boor basis ----
        int e = threadIdx.x;             // 1024 threads
        float u = (float)(EPS_ + (double)e * ((1.0 - 2.0 * EPS_) / 1023.0));

        // searchsorted(knots, u, 'right') - 1
        int lo = 0, hi = KLEN;
        while (lo < hi) {
            int mid = (lo + hi) >> 1;
            if (kn[mid] <= u) lo = mid + 1; else hi = mid;
        }
        int span = lo - 1;
        if (u == kn[N_CTRL]) span = N_CTRL - 1;

        float left[DEG + 1], right[DEG + 1], N[DEG + 1];
        N[0] = 1.f;
        #pragma unroll
        for (int j = 1; j <= DEG; j++) {
            left[j]  = u - kn[imod(span + 1 - j, KLEN)];
            right[j] = kn[imod(span + j, KLEN)] - u;
            float saved = 0.f;
            #pragma unroll
            for (int r = 0; r < j; r++) {
                float temp = N[r] / (right[r + 1] + left[j - r]);
                N[r]  = saved + right[r + 1] * temp;
                saved = left[j - r] * temp;
            }
            N[j] = saved;
        }

        float4 bb = make_float4(N[0], N[1], N[2], N[3]);
        int4 ii;
        ii.x = imod(span - DEG + 0, N_CTRL);
        ii.y = imod(span - DEG + 1, N_CTRL);
        ii.z = imod(span - DEG + 2, N_CTRL);
        ii.w = imod(span - DEG + 3, N_CTRL);

        if (b == 0) { g_bx[e] = bb; g_ix[e] = ii; }
        else        { g_by[e] = bb; g_iy[e] = ii; }
    } else {
        // ---- pack control points: blocks 2..65, 1024 threads each ----
        int idx = (b - 2) * 1024 + threadIdx.x;   // 0..65535
        const float* p = cp + (size_t)idx * 3;
        g_cp4[idx] = make_float4(p[0], p[1], p[2], 0.f);
    }
}

// ---------------- kernel 2: pass 1 : T[i][f] = sum_r by[f][r]*cp4[i][iy_r]
// grid (4, 128), block 256. Each thread: fixed f, 2 consecutive rows i.
// 512 blocks -> ~27 warps/SM, latency fully hidden.
__global__ void pass1_kernel() {
    int f  = blockIdx.x * blockDim.x + threadIdx.x;  // 0..1023
    int i0 = blockIdx.y * 2;
    float4 by = g_by[f];
    int4   iy = g_iy[f];
    #pragma unroll
    for (int k = 0; k < 2; k++) {
        int i = i0 + k;
        const float4* __restrict__ row = g_cp4 + i * N_CTRL;
        float4 a = row[iy.x];
        float4 bq = row[iy.y];
        float4 c = row[iy.z];
        float4 d = row[iy.w];
        float4 t;
        t.x = by.x * a.x + by.y * bq.x + by.z * c.x + by.w * d.x;
        t.y = by.x * a.y + by.y * bq.y + by.z * c.y + by.w * d.y;
        t.z = by.x * a.z + by.y * bq.z + by.z * c.z + by.w * d.z;
        t.w = 0.f;
        g_T[i * OUT_Y + f] = t;
    }
}

// ---------------- kernel 3: pass 2 : out[e][f] = sum_l bx[e][l]*T[ix_l][f]
// grid 256: each block handles 4 consecutive e values over all 1024 f.
// Consecutive e share most T rows -> same per-thread addresses repeat
// across the e loop -> L1 hits (block row working set ~6x16KB < L1).
__global__ void pass2_kernel(float* __restrict__ out) {
    int e0 = blockIdx.x * 4;
    int f0 = threadIdx.x * 4;

    #pragma unroll
    for (int ei = 0; ei < 4; ei++) {
        int e = e0 + ei;
        float4 bx = g_bx[e];
        int4   ix = g_ix[e];

        float bw[4] = {bx.x, bx.y, bx.z, bx.w};
        int   ir[4] = {ix.x, ix.y, ix.z, ix.w};

        float4 a0 = make_float4(0, 0, 0, 0);
        float4 a1 = make_float4(0, 0, 0, 0);
        float4 a2 = make_float4(0, 0, 0, 0);
        float4 a3 = make_float4(0, 0, 0, 0);

        #pragma unroll
        for (int l = 0; l < 4; l++) {
            const float4* __restrict__ r = g_T + (size_t)ir[l] * OUT_Y + f0;
            float w = bw[l];
            float4 v0 = r[0], v1 = r[1], v2 = r[2], v3 = r[3];
            a0.x += w * v0.x; a0.y += w * v0.y; a0.z += w * v0.z;
            a1.x += w * v1.x; a1.y += w * v1.y; a1.z += w * v1.z;
            a2.x += w * v2.x; a2.y += w * v2.y; a2.z += w * v2.z;
            a3.x += w * v3.x; a3.y += w * v3.y; a3.z += w * v3.z;
        }

        float* o = out + ((size_t)e * OUT_Y + f0) * 3;
        float4 o0 = make_float4(a0.x, a0.y, a0.z, a1.x);
        float4 o1 = make_float4(a1.y, a1.z, a2.x, a2.y);
        float4 o2 = make_float4(a2.z, a3.x, a3.y, a3.z);
        reinterpret_cast<float4*>(o)[0] = o0;
        reinterpret_cast<float4*>(o)[1] = o1;
        reinterpret_cast<float4*>(o)[2] = o2;
    }
}

// ---------------------------- launch --------------------------------------
extern "C" void kernel_launch(void* const* d_in, const int* in_sizes, int n_in,
                              void* d_out, int out_size) {
    const float* cp = (const float*)d_in[0];
    const float* kx = (const float*)d_in[1];
    const float* ky = (const float*)d_in[2];
    float* out = (float*)d_out;

    prep_kernel<<<66, 1024>>>(cp, kx, ky);
    {
        dim3 grid(4, 128);
        pass1_kernel<<<grid, 256>>>();
    }
    pass2_kernel<<<256, 256>>>(out);
}

// round 13
// speedup vs baseline: 1.1265x; 1.1265x over previous
#include <cuda_runtime.h>
#include <cstdint>

#define N_CTRL   256
#define KLEN     260     // N_CTRL + DEGREE + 1
#define OUT_X    1024
#define OUT_Y    1024
#define DEG      3
#define EPS_     1e-05

// ---------------- device scratch (no allocations allowed) ----------------
__device__ float4 g_bx[OUT_X];
__device__ float4 g_by[OUT_Y];
__device__ int4   g_ix[OUT_X];
__device__ int4   g_iy[OUT_Y];
__device__ float4 g_cp4[N_CTRL * N_CTRL];        // 1 MB packed control points
__device__ float4 g_T[N_CTRL * OUT_Y];           // 4 MB intermediate T[i][f]

__device__ __forceinline__ int imod(int a, int m) {
    int r = a % m;
    return r < 0 ? r + m : r;
}

// ---------------- kernel 1: fused prep --------------------------------
// blocks 0,1 : normalize knots (parallel 2-level scan) + basis + indices
// blocks 2..65 : pack control points into float4
__global__ void prep_kernel(const float* __restrict__ cp,
                            const float* __restrict__ kx_in,
                            const float* __restrict__ ky_in) {
    int b = blockIdx.x;
    if (b < 2) {
        __shared__ float kn[KLEN];
        __shared__ float wtot[16];
        const float* in = (b == 0) ? kx_in : ky_in;

        int t    = threadIdx.x;
        int lane = t & 31;
        int w    = t >> 5;

        // ---- parallel load (one coalesced burst) + clamp ----
        float v = 0.f;
        if (t < KLEN) {
            v = in[t];
            if (v < 0.f) v = 1e-4f;     // jnp.where(k < 0, 0.0001, k)
        }

        // ---- level 1: per-warp inclusive scan (warps 0..8 cover 260) ----
        float vs = v;
        if (w < 9) {
            #pragma unroll
            for (int off = 1; off < 32; off <<= 1) {
                float n = __shfl_up_sync(0xffffffffu, vs, off);
                if (lane >= off) vs += n;
            }
            if (lane == 31) wtot[w] = vs;
        }
        __syncthreads();

        // ---- level 2: warp 0 scans the 9 warp totals ----
        if (t < 32) {
            float tv = (t < 9) ? wtot[t] : 0.f;
            #pragma unroll
            for (int off = 1; off < 16; off <<= 1) {
                float n = __shfl_up_sync(0xffffffffu, tv, off);
                if (lane >= off) tv += n;
            }
            if (t < 9) wtot[t] = tv;    // inclusive totals
        }
        __syncthreads();

        // ---- combine -> full inclusive cumsum in smem ----
        if (t < KLEN) {
            float pre = (w > 0) ? wtot[w - 1] : 0.f;
            kn[t] = vs + pre;
        }
        __syncthreads();

        // ---- normalize in place ----
        float k0  = kn[0];
        float inv = 1.f / (kn[KLEN - 1] - k0);
        __syncthreads();                 // everyone read k0/kend before writes
        if (t < KLEN) kn[t] = (kn[t] - k0) * inv;
        __syncthreads();

        // ---- per-sample span + Cox-de Boor basis ----
        int e = t;                       // 1024 threads
        float u = (float)(EPS_ + (double)e * ((1.0 - 2.0 * EPS_) / 1023.0));

        // searchsorted(knots, u, 'right') - 1
        int lo = 0, hi = KLEN;
        while (lo < hi) {
            int mid = (lo + hi) >> 1;
            if (kn[mid] <= u) lo = mid + 1; else hi = mid;
        }
        int span = lo - 1;
        if (u == kn[N_CTRL]) span = N_CTRL - 1;

        float left[DEG + 1], right[DEG + 1], N[DEG + 1];
        N[0] = 1.f;
        #pragma unroll
        for (int j = 1; j <= DEG; j++) {
            left[j]  = u - kn[imod(span + 1 - j, KLEN)];
            right[j] = kn[imod(span + j, KLEN)] - u;
            float saved = 0.f;
            #pragma unroll
            for (int r = 0; r < j; r++) {
                float temp = N[r] / (right[r + 1] + left[j - r]);
                N[r]  = saved + right[r + 1] * temp;
                saved = left[j - r] * temp;
            }
            N[j] = saved;
        }

        float4 bb = make_float4(N[0], N[1], N[2], N[3]);
        int4 ii;
        ii.x = imod(span - DEG + 0, N_CTRL);
        ii.y = imod(span - DEG + 1, N_CTRL);
        ii.z = imod(span - DEG + 2, N_CTRL);
        ii.w = imod(span - DEG + 3, N_CTRL);

        if (b == 0) { g_bx[e] = bb; g_ix[e] = ii; }
        else        { g_by[e] = bb; g_iy[e] = ii; }
    } else {
        // ---- pack control points: blocks 2..65, 1024 threads each ----
        int idx = (b - 2) * 1024 + threadIdx.x;   // 0..65535
        const float* p = cp + (size_t)idx * 3;
        g_cp4[idx] = make_float4(p[0], p[1], p[2], 0.f);
    }
}

// ---------------- kernel 2: pass 1 : T[i][f] = sum_r by[f][r]*cp4[i][iy_r]
// grid (4, 128), block 256. Each thread: fixed f, 2 consecutive rows i.
__global__ void pass1_kernel() {
    int f  = blockIdx.x * blockDim.x + threadIdx.x;  // 0..1023
    int i0 = blockIdx.y * 2;
    float4 by = g_by[f];
    int4   iy = g_iy[f];
    #pragma unroll
    for (int k = 0; k < 2; k++) {
        int i = i0 + k;
        const float4* __restrict__ row = g_cp4 + i * N_CTRL;
        float4 a  = row[iy.x];
        float4 bq = row[iy.y];
        float4 c  = row[iy.z];
        float4 d  = row[iy.w];
        float4 t;
        t.x = by.x * a.x + by.y * bq.x + by.z * c.x + by.w * d.x;
        t.y = by.x * a.y + by.y * bq.y + by.z * c.y + by.w * d.y;
        t.z = by.x * a.z + by.y * bq.z + by.z * c.z + by.w * d.z;
        t.w = 0.f;
        g_T[i * OUT_Y + f] = t;
    }
}

// ---------------- kernel 3: pass 2 : out[e][f] = sum_l bx[e][l]*T[ix_l][f]
// grid 256: each block handles 4 consecutive e values over all 1024 f.
__global__ void pass2_kernel(float* __restrict__ out) {
    int e0 = blockIdx.x * 4;
    int f0 = threadIdx.x * 4;

    #pragma unroll
    for (int ei = 0; ei < 4; ei++) {
        int e = e0 + ei;
        float4 bx = g_bx[e];
        int4   ix = g_ix[e];

        float bw[4] = {bx.x, bx.y, bx.z, bx.w};
        int   ir[4] = {ix.x, ix.y, ix.z, ix.w};

        float4 a0 = make_float4(0, 0, 0, 0);
        float4 a1 = make_float4(0, 0, 0, 0);
        float4 a2 = make_float4(0, 0, 0, 0);
        float4 a3 = make_float4(0, 0, 0, 0);

        #pragma unroll
        for (int l = 0; l < 4; l++) {
            const float4* __restrict__ r = g_T + (size_t)ir[l] * OUT_Y + f0;
            float w = bw[l];
            float4 v0 = r[0], v1 = r[1], v2 = r[2], v3 = r[3];
            a0.x += w * v0.x; a0.y += w * v0.y; a0.z += w * v0.z;
            a1.x += w * v1.x; a1.y += w * v1.y; a1.z += w * v1.z;
            a2.x += w * v2.x; a2.y += w * v2.y; a2.z += w * v2.z;
            a3.x += w * v3.x; a3.y += w * v3.y; a3.z += w * v3.z;
        }

        float* o = out + ((size_t)e * OUT_Y + f0) * 3;
        float4 o0 = make_float4(a0.x, a0.y, a0.z, a1.x);
        float4 o1 = make_float4(a1.y, a1.z, a2.x, a2.y);
        float4 o2 = make_float4(a2.z, a3.x, a3.y, a3.z);
        reinterpret_cast<float4*>(o)[0] = o0;
        reinterpret_cast<float4*>(o)[1] = o1;
        reinterpret_cast<float4*>(o)[2] = o2;
    }
}

// ---------------------------- launch --------------------------------------
extern "C" void kernel_launch(void* const* d_in, const int* in_sizes, int n_in,
                              void* d_out, int out_size) {
    const float* cp = (const float*)d_in[0];
    const float* kx = (const float*)d_in[1];
    const float* ky = (const float*)d_in[2];
    float* out = (float*)d_out;

    prep_kernel<<<66, 1024>>>(cp, kx, ky);
    {
        dim3 grid(4, 128);
        pass1_kernel<<<grid, 256>>>();
    }
    pass2_kernel<<<256, 256>>>(out);
}

// round 14
// speedup vs baseline: 1.1420x; 1.0137x over previous
#include <cuda_runtime.h>
#include <cstdint>

#define N_CTRL   256
#define KLEN     260     // N_CTRL + DEGREE + 1
#define OUT_X    1024
#define OUT_Y    1024
#define DEG      3
#define EPS_     1e-05f

// ---------------- device scratch (no allocations allowed) ----------------
__device__ float4 g_bx[OUT_X];
__device__ float4 g_by[OUT_Y];
__device__ int4   g_ix[OUT_X];
__device__ int4   g_iy[OUT_Y];
__device__ float4 g_cp4[N_CTRL * N_CTRL];        // 1 MB packed control points
__device__ float4 g_T[N_CTRL * OUT_Y];           // 4 MB intermediate T[i][f]

__device__ __forceinline__ int imod(int a, int m) {
    int r = a % m;
    return r < 0 ? r + m : r;
}

// ---------------- kernel 1: fused prep --------------------------------
// blocks 0,1 : normalize knots (parallel 2-level scan) + basis + indices
// blocks 2..65 : pack control points into float4
__global__ void prep_kernel(const float* __restrict__ cp,
                            const float* __restrict__ kx_in,
                            const float* __restrict__ ky_in) {
    int b = blockIdx.x;
    if (b < 2) {
        __shared__ float kn[KLEN];
        __shared__ float wtot[16];
        const float* in = (b == 0) ? kx_in : ky_in;

        int t    = threadIdx.x;
        int lane = t & 31;
        int w    = t >> 5;

        // ---- parallel load (one coalesced burst) + clamp ----
        float v = 0.f;
        if (t < KLEN) {
            v = in[t];
            if (v < 0.f) v = 1e-4f;     // jnp.where(k < 0, 0.0001, k)
        }

        // ---- level 1: per-warp inclusive scan (warps 0..8 cover 260) ----
        float vs = v;
        if (w < 9) {
            #pragma unroll
            for (int off = 1; off < 32; off <<= 1) {
                float n = __shfl_up_sync(0xffffffffu, vs, off);
                if (lane >= off) vs += n;
            }
            if (lane == 31) wtot[w] = vs;
        }
        __syncthreads();

        // ---- level 2: warp 0 scans the 9 warp totals ----
        if (t < 32) {
            float tv = (t < 9) ? wtot[t] : 0.f;
            #pragma unroll
            for (int off = 1; off < 16; off <<= 1) {
                float n = __shfl_up_sync(0xffffffffu, tv, off);
                if (lane >= off) tv += n;
            }
            if (t < 9) wtot[t] = tv;    // inclusive totals
        }
        __syncthreads();

        // ---- combine -> full inclusive cumsum in smem ----
        if (t < KLEN) {
            float pre = (w > 0) ? wtot[w - 1] : 0.f;
            kn[t] = vs + pre;
        }
        __syncthreads();

        // ---- normalize in place ----
        float k0  = kn[0];
        float inv = __fdividef(1.f, kn[KLEN - 1] - k0);
        __syncthreads();                 // everyone read k0/kend before writes
        if (t < KLEN) kn[t] = (kn[t] - k0) * inv;
        __syncthreads();

        // ---- per-sample span + Cox-de Boor basis (all float32) ----
        int e = t;                       // 1024 threads
        // linspace(EPS, 1-EPS, 1024) in f32 (matches f32 reference)
        const float step = (1.0f - 2.0f * EPS_) / 1023.0f;
        float u = EPS_ + (float)e * step;

        // searchsorted(knots, u, 'right') - 1
        int lo = 0, hi = KLEN;
        while (lo < hi) {
            int mid = (lo + hi) >> 1;
            if (kn[mid] <= u) lo = mid + 1; else hi = mid;
        }
        int span = lo - 1;
        if (u == kn[N_CTRL]) span = N_CTRL - 1;

        float left[DEG + 1], right[DEG + 1], N[DEG + 1];
        N[0] = 1.f;
        #pragma unroll
        for (int j = 1; j <= DEG; j++) {
            left[j]  = u - kn[imod(span + 1 - j, KLEN)];
            right[j] = kn[imod(span + j, KLEN)] - u;
            float saved = 0.f;
            #pragma unroll
            for (int r = 0; r < j; r++) {
                float temp = __fdividef(N[r], right[r + 1] + left[j - r]);
                N[r]  = saved + right[r + 1] * temp;
                saved = left[j - r] * temp;
            }
            N[j] = saved;
        }

        float4 bb = make_float4(N[0], N[1], N[2], N[3]);
        int4 ii;
        ii.x = imod(span - DEG + 0, N_CTRL);
        ii.y = imod(span - DEG + 1, N_CTRL);
        ii.z = imod(span - DEG + 2, N_CTRL);
        ii.w = imod(span - DEG + 3, N_CTRL);

        if (b == 0) { g_bx[e] = bb; g_ix[e] = ii; }
        else        { g_by[e] = bb; g_iy[e] = ii; }
    } else {
        // ---- pack control points: blocks 2..65, 1024 threads each ----
        int idx = (b - 2) * 1024 + threadIdx.x;   // 0..65535
        const float* p = cp + (size_t)idx * 3;
        g_cp4[idx] = make_float4(p[0], p[1], p[2], 0.f);
    }
}

// ---------------- kernel 2: pass 1 : T[i][f] = sum_r by[f][r]*cp4[i][iy_r]
// grid (4, 128), block 256. Each thread: fixed f, 2 consecutive rows i.
__global__ void pass1_kernel() {
    int f  = blockIdx.x * blockDim.x + threadIdx.x;  // 0..1023
    int i0 = blockIdx.y * 2;
    float4 by = g_by[f];
    int4   iy = g_iy[f];
    #pragma unroll
    for (int k = 0; k < 2; k++) {
        int i = i0 + k;
        const float4* __restrict__ row = g_cp4 + i * N_CTRL;
        float4 a  = row[iy.x];
        float4 bq = row[iy.y];
        float4 c  = row[iy.z];
        float4 d  = row[iy.w];
        float4 t;
        t.x = by.x * a.x + by.y * bq.x + by.z * c.x + by.w * d.x;
        t.y = by.x * a.y + by.y * bq.y + by.z * c.y + by.w * d.y;
        t.z = by.x * a.z + by.y * bq.z + by.z * c.z + by.w * d.z;
        t.w = 0.f;
        g_T[i * OUT_Y + f] = t;
    }
}

// ---------------- kernel 3: pass 2 : out[e][f] = sum_l bx[e][l]*T[ix_l][f]
// grid 256: each block handles 4 consecutive e values over all 1024 f.
__global__ void pass2_kernel(float* __restrict__ out) {
    int e0 = blockIdx.x * 4;
    int f0 = threadIdx.x * 4;

    #pragma unroll
    for (int ei = 0; ei < 4; ei++) {
        int e = e0 + ei;
        float4 bx = g_bx[e];
        int4   ix = g_ix[e];

        float bw[4] = {bx.x, bx.y, bx.z, bx.w};
        int   ir[4] = {ix.x, ix.y, ix.z, ix.w};

        float4 a0 = make_float4(0, 0, 0, 0);
        float4 a1 = make_float4(0, 0, 0, 0);
        float4 a2 = make_float4(0, 0, 0, 0);
        float4 a3 = make_float4(0, 0, 0, 0);

        #pragma unroll
        for (int l = 0; l < 4; l++) {
            const float4* __restrict__ r = g_T + (size_t)ir[l] * OUT_Y + f0;
            float w = bw[l];
            float4 v0 = r[0], v1 = r[1], v2 = r[2], v3 = r[3];
            a0.x += w * v0.x; a0.y += w * v0.y; a0.z += w * v0.z;
            a1.x += w * v1.x; a1.y += w * v1.y; a1.z += w * v1.z;
            a2.x += w * v2.x; a2.y += w * v2.y; a2.z += w * v2.z;
            a3.x += w * v3.x; a3.y += w * v3.y; a3.z += w * v3.z;
        }

        float* o = out + ((size_t)e * OUT_Y + f0) * 3;
        float4 o0 = make_float4(a0.x, a0.y, a0.z, a1.x);
        float4 o1 = make_float4(a1.y, a1.z, a2.x, a2.y);
        float4 o2 = make_float4(a2.z, a3.x, a3.y, a3.z);
        reinterpret_cast<float4*>(o)[0] = o0;
        reinterpret_cast<float4*>(o)[1] = o1;
        reinterpret_cast<float4*>(o)[2] = o2;
    }
}

// ---------------------------- launch --------------------------------------
extern "C" void kernel_launch(void* const* d_in, const int* in_sizes, int n_in,
                              void* d_out, int out_size) {
    const float* cp = (const float*)d_in[0];
    const float* kx = (const float*)d_in[1];
    const float* ky = (const float*)d_in[2];
    float* out = (float*)d_out;

    prep_kernel<<<66, 1024>>>(cp, kx, ky);
    {
        dim3 grid(4, 128);
        pass1_kernel<<<grid, 256>>>();
    }
    pass2_kernel<<<256, 256>>>(out);
}